// round 16
// baseline (speedup 1.0000x reference)
#include <cuda_runtime.h>
#include <math.h>
#include <stdint.h>

#define NB 1576
#define NT 30
#define ND 1024
#define NH 128
#define NM (NB*NT)   // 47280

// scratch
__device__ float g_h  [(size_t)NM * NH];
__device__ float g_hg [(size_t)NM * NH];
__device__ float g_o  [(size_t)NM * NH];
__device__ float g_W1r[(size_t)ND * NH];
__device__ float g_W2r[(size_t)NH * ND];
__device__ float g_Wor[(size_t)NH * NH];
__device__ float g_Wqkvr[(size_t)NH * 384];
__device__ float g_bqkv[384];

__device__ __forceinline__ uint32_t smem_u32(const void* p) {
    uint32_t a;
    asm("{ .reg .u64 t; cvta.to.shared.u64 t, %1; cvt.u32.u64 %0, t; }" : "=r"(a) : "l"(p));
    return a;
}
__device__ __forceinline__ uint32_t f2tf32(float f) {
    uint32_t r; asm("cvt.rna.tf32.f32 %0, %1;" : "=r"(r) : "f"(f)); return r;
}
__device__ __forceinline__ float f2tf32f(float f) { return __uint_as_float(f2tf32(f)); }
__device__ __forceinline__ uint32_t cvt_raw_tf32(uint32_t raw) {
    uint32_t r; asm("cvt.rna.tf32.f32 %0, %1;" : "=r"(r) : "f"(__uint_as_float(raw)));
    return r;
}
__device__ __forceinline__ void sts128(uint32_t a, uint32_t x, uint32_t y, uint32_t z, uint32_t w) {
    asm volatile("st.shared.v4.b32 [%0], {%1,%2,%3,%4};" :: "r"(a), "r"(x), "r"(y), "r"(z), "r"(w));
}
__device__ __forceinline__ uint32_t lds_u(uint32_t a) {
    uint32_t v; asm volatile("ld.shared.b32 %0, [%1];" : "=r"(v) : "r"(a)); return v;
}
__device__ __forceinline__ void cp16(uint32_t dst, const void* src) {
    asm volatile("cp.async.cg.shared.global [%0], [%1], 16;" :: "r"(dst), "l"(src));
}
__device__ __forceinline__ void cp16z(uint32_t dst, const void* src, uint32_t sz) {
    asm volatile("cp.async.cg.shared.global [%0], [%1], 16, %2;"
                 :: "r"(dst), "l"(src), "r"(sz));
}
#define CP_COMMIT() asm volatile("cp.async.commit_group;" ::: "memory")
#define CP_WAIT0()  asm volatile("cp.async.wait_group 0;" ::: "memory")

#define LDA_S 36
#define LDB_S 136
#define LDE_S 132
#define LDH   132
#define M1    160
#define GM1   296

#define K1_A0   0
#define K1_A1   (M1*LDA_S)
#define K1_B0   (2*M1*LDA_S)
#define K1_B1   (2*M1*LDA_S + 32*LDB_S)
#define K1_UNION 21120
struct SmemG1 {
    float u[K1_UNION];
    float parb[128];
    float parg[128];
    float parbt[128];
    float mean[M1];
    float rstd[M1];
};
struct SmemO2 {
    float u[K1_UNION];
    float Bb[32 * LDB_S];
    float parb[128];
};
// fused gate+qkv+attention kernel (~212 KB, 1 block/SM)
struct SmemF {
    float hn[128 * LDH];       // h -> LN'd A-operand -> (after ntile2) v
    float kT[128 * LDH];       // k transposed: kT[col*LDH + row]
    float q [120 * 128];       // q row-major
    union {
        float Bb[32 * LDB_S];  // B staging during qkv GEMM
        float sc[120 * 32];    // softmax'd scores after GEMM
    } w;
    float rowm[120];
    float gate[120];
    float parb[384];
};

__global__ void k_prep(const float* __restrict__ W1, const float* __restrict__ W2,
                       const float* __restrict__ Wo,
                       const float* __restrict__ Wq, const float* __restrict__ Wk,
                       const float* __restrict__ Wv,
                       const float* __restrict__ bq, const float* __restrict__ bk,
                       const float* __restrict__ bv) {
    int i = blockIdx.x * 256 + threadIdx.x;
    const int N1 = ND * NH, N2 = NH * ND, N3 = NH * NH, N4 = 3 * NH * NH;
    if (i < N1) {
        g_W1r[i] = f2tf32f(W1[i]);
    } else if (i < N1 + N2) {
        int j = i - N1;
        g_W2r[j] = f2tf32f(W2[j]);
    } else if (i < N1 + N2 + N3) {
        int j = i - N1 - N2;
        g_Wor[j] = f2tf32f(Wo[j]);
    } else if (i < N1 + N2 + N3 + N4) {
        int j = i - N1 - N2 - N3;
        int m = j / (NH * NH);
        int r = (j / NH) % NH;
        int n = j % NH;
        const float* W = (m == 0) ? Wq : (m == 1) ? Wk : Wv;
        g_Wqkvr[(size_t)r * 384 + m * NH + n] = f2tf32f(W[(size_t)r * NH + n]);
    } else if (i < N1 + N2 + N3 + N4 + 384) {
        int j = i - N1 - N2 - N3 - N4;
        int m = j / NH, n = j % NH;
        const float* bb = (m == 0) ? bq : (m == 1) ? bk : bv;
        g_bqkv[j] = bb[n];
    }
}

__device__ __forceinline__ void cpA(uint32_t As, const float* __restrict__ Ag,
                                    int ldA, int row0, int k0, int tid) {
#pragma unroll
    for (int q = 0; q < 5; q++) {
        int idx = tid + 256 * q;
        int r = idx >> 3, j = idx & 7;
        int row = row0 + r;
        uint32_t sz = (row < NM) ? 16u : 0u;
        const float* src = Ag + (size_t)(row < NM ? row : 0) * ldA + k0 + j * 4;
        cp16z(As + (r * LDA_S + j * 4) * 4, src, sz);
    }
}
__device__ __forceinline__ void cpB(uint32_t Bs, const float* __restrict__ Bg,
                                    int ldB, int bn0, int k0, int tid) {
#pragma unroll
    for (int q = 0; q < 4; q++) {
        int idx = tid + 256 * q;
        int kk = idx >> 5, jc = idx & 31;
        cp16(Bs + (kk * LDB_S + jc * 4) * 4,
             Bg + (size_t)(k0 + kk) * ldB + bn0 + jc * 4);
    }
}

template<int MT, int LD, bool CVT>
__device__ __forceinline__ void mm_frag(uint32_t Ab, uint32_t Bs, int kbase,
                                        int lane, int wm, int wn,
                                        float acc[MT][4][4]) {
    int tr = lane >> 2, tc = lane & 3;
#pragma unroll
    for (int ks = 0; ks < 4; ks++) {
        int ka = kbase + ks * 8;
        int kb = ks * 8;
        uint32_t af[MT][4];
#pragma unroll
        for (int mt = 0; mt < MT; mt++) {
            int row = wm + mt * 16 + tr;
            uint32_t b0 = Ab + (row * LD + ka + tc) * 4;
            af[mt][0] = lds_u(b0);
            af[mt][1] = lds_u(b0 + 8 * LD * 4);
            af[mt][2] = lds_u(b0 + 16);
            af[mt][3] = lds_u(b0 + 8 * LD * 4 + 16);
            if (CVT) {
                af[mt][0] = cvt_raw_tf32(af[mt][0]);
                af[mt][1] = cvt_raw_tf32(af[mt][1]);
                af[mt][2] = cvt_raw_tf32(af[mt][2]);
                af[mt][3] = cvt_raw_tf32(af[mt][3]);
            }
        }
        uint32_t bf[4][2];
#pragma unroll
        for (int nt = 0; nt < 4; nt++) {
            int col = wn + nt * 8 + tr;
            uint32_t b0 = Bs + ((kb + tc) * LDB_S + col) * 4;
            bf[nt][0] = lds_u(b0);
            bf[nt][1] = lds_u(b0 + 4 * LDB_S * 4);
        }
#pragma unroll
        for (int mt = 0; mt < MT; mt++)
#pragma unroll
            for (int nt = 0; nt < 4; nt++)
                asm volatile(
                    "mma.sync.aligned.m16n8k8.row.col.f32.tf32.tf32.f32 "
                    "{%0,%1,%2,%3}, {%4,%5,%6,%7}, {%8,%9}, {%0,%1,%2,%3};"
                    : "+f"(acc[mt][nt][0]), "+f"(acc[mt][nt][1]),
                      "+f"(acc[mt][nt][2]), "+f"(acc[mt][nt][3])
                    : "r"(af[mt][0]), "r"(af[mt][1]), "r"(af[mt][2]), "r"(af[mt][3]),
                      "r"(bf[nt][0]), "r"(bf[nt][1]));
    }
}

#define ACC_INIT5(acc) \
    _Pragma("unroll") for (int a_ = 0; a_ < 5; a_++) \
    _Pragma("unroll") for (int b_ = 0; b_ < 4; b_++) { \
        acc[a_][b_][0]=0.f; acc[a_][b_][1]=0.f; acc[a_][b_][2]=0.f; acc[a_][b_][3]=0.f; }
#define ACC_INIT4(acc) \
    _Pragma("unroll") for (int a_ = 0; a_ < 4; a_++) \
    _Pragma("unroll") for (int b_ = 0; b_ < 4; b_++) { \
        acc[a_][b_][0]=0.f; acc[a_][b_][1]=0.f; acc[a_][b_][2]=0.f; acc[a_][b_][3]=0.f; }

// ---------------------------------------------------------------------------
// GEMM1 (unchanged R15 winner)
// ---------------------------------------------------------------------------
__global__ __launch_bounds__(256, 2) void k1_mma(
    const float* __restrict__ x, const float* __restrict__ b1,
    const float* __restrict__ ln_g, const float* __restrict__ ln_b)
{
    extern __shared__ char smraw[];
    SmemG1* s = (SmemG1*)smraw;
    int tid = threadIdx.x;
    int lane = tid & 31, wid = tid >> 5;
    int row0 = blockIdx.x * M1;
    int wm = (wid >> 2) * 80, wn = (wid & 3) * 32;

    if (tid < 128) {
        s->parb[tid]  = b1[tid];
        s->parg[tid]  = ln_g[tid];
        s->parbt[tid] = ln_b[tid];
    }
    uint32_t ub = smem_u32(&s->u[0]);
    uint32_t aA[2] = { ub + K1_A0 * 4, ub + K1_A1 * 4 };
    uint32_t aB[2] = { ub + K1_B0 * 4, ub + K1_B1 * 4 };

    float acc[5][4][4];
    ACC_INIT5(acc);

    cpA(aA[0], x, ND, row0, 0, tid);
    cpB(aB[0], g_W1r, NH, 0, 0, tid);
    CP_COMMIT(); CP_WAIT0();
    __syncthreads();

    int buf = 0;
    for (int it = 0; it < ND / 32; it++) {
        bool pf = (it + 1 < ND / 32);
        if (pf) {
            cpA(aA[buf ^ 1], x, ND, row0, (it + 1) * 32, tid);
            cpB(aB[buf ^ 1], g_W1r, NH, 0, (it + 1) * 32, tid);
            CP_COMMIT();
        }
        mm_frag<5, LDA_S, true>(aA[buf], aB[buf], 0, lane, wm, wn, acc);
        CP_WAIT0();
        __syncthreads();
        buf ^= 1;
    }

    int tr = lane >> 2, tc = lane & 3;
    float* epi = s->u;
#pragma unroll
    for (int mt = 0; mt < 5; mt++) {
#pragma unroll
        for (int nt = 0; nt < 4; nt++) {
            int row = wm + mt * 16 + tr;
            int col = wn + nt * 8 + 2 * tc;
            float bb0 = s->parb[col], bb1 = s->parb[col + 1];
            epi[row * LDE_S + col]           = acc[mt][nt][0] + bb0;
            epi[row * LDE_S + col + 1]       = acc[mt][nt][1] + bb1;
            epi[(row + 8) * LDE_S + col]     = acc[mt][nt][2] + bb0;
            epi[(row + 8) * LDE_S + col + 1] = acc[mt][nt][3] + bb1;
        }
    }
    __syncthreads();

    for (int r = wid; r < M1; r += 8) {
        float x0 = epi[r * LDE_S + lane];
        float x1 = epi[r * LDE_S + lane + 32];
        float x2 = epi[r * LDE_S + lane + 64];
        float x3 = epi[r * LDE_S + lane + 96];
        float su = x0 + x1 + x2 + x3;
        float sq = x0 * x0 + x1 * x1 + x2 * x2 + x3 * x3;
#pragma unroll
        for (int o = 16; o; o >>= 1) {
            su += __shfl_xor_sync(0xffffffffu, su, o);
            sq += __shfl_xor_sync(0xffffffffu, sq, o);
        }
        float mean = su * (1.f / 128.f);
        float var  = sq * (1.f / 128.f) - mean * mean;
        if (lane == 0) {
            s->mean[r] = mean;
            s->rstd[r] = rsqrtf(fmaxf(var, 0.f) + 1e-5f);
        }
    }
    __syncthreads();

#pragma unroll
    for (int q = 0; q < 20; q++) {
        int idx = tid + 256 * q;
        int r = idx >> 5, c4 = idx & 31;
        int row = row0 + r;
        if (row < NM) {
            float4 v = *(float4*)&epi[r * LDE_S + 4 * c4];
            float mean = s->mean[r], rstd = s->rstd[r];
            float4 gv = *(float4*)&s->parg[4 * c4];
            float4 bv = *(float4*)&s->parbt[4 * c4];
            float4 o;
            o.x = (v.x - mean) * rstd * gv.x + bv.x;
            o.y = (v.y - mean) * rstd * gv.y + bv.y;
            o.z = (v.z - mean) * rstd * gv.z + bv.z;
            o.w = (v.w - mean) * rstd * gv.w + bv.w;
            *(float4*)(g_h + (size_t)row * NH + 4 * c4) = o;
        }
    }
}

// ---------------------------------------------------------------------------
// k_gateatt: gate + LN + qkv GEMM + attention, fully fused. 4 batches/block.
// ---------------------------------------------------------------------------
__global__ __launch_bounds__(256) void k_gateatt(
    const float* __restrict__ T_W, const float* __restrict__ T_b,
    const float* __restrict__ n_g, const float* __restrict__ n_b)
{
    extern __shared__ char smraw[];
    SmemF* s = (SmemF*)smraw;
    int tid = threadIdx.x;
    int lane = tid & 31, wid = tid >> 5;
    int row0 = blockIdx.x * 4 * NT;   // 120 rows
    const float* hgld = g_h + (size_t)row0 * NH;

    for (int i = tid; i < 384; i += 256) s->parb[i] = g_bqkv[i];

    // ---- load h, zero pad rows ----
    for (int idx = tid; idx < 120 * 32; idx += 256) {
        int r = idx >> 5, c4 = idx & 31;
        float4 t = *(const float4*)(hgld + (size_t)r * NH + 4 * c4);
        *(float4*)&s->hn[r * LDH + 4 * c4] = t;
    }
    for (int idx = tid; idx < 8 * 32; idx += 256) {
        int r = 120 + (idx >> 5), c4 = idx & 31;
        *(float4*)&s->hn[r * LDH + 4 * c4] = make_float4(0.f, 0.f, 0.f, 0.f);
    }
    __syncthreads();

    // ---- row means ----
    for (int r = wid; r < 120; r += 8) {
        float a = s->hn[r * LDH + lane] + s->hn[r * LDH + lane + 32]
                + s->hn[r * LDH + lane + 64] + s->hn[r * LDH + lane + 96];
#pragma unroll
        for (int o = 16; o; o >>= 1) a += __shfl_xor_sync(0xffffffffu, a, o);
        if (lane == 0) s->rowm[r] = a * (1.f / 128.f);
    }
    __syncthreads();

    // ---- gate softmax per batch ----
    if (wid < 4) {
        int bi = wid;
        float val = -1e30f;
        if (lane < NT) {
            float a = T_b[lane];
#pragma unroll
            for (int u = 0; u < NT; u++) a += s->rowm[bi * NT + u] * T_W[u * NT + lane];
            val = a;
        }
        float m = val;
#pragma unroll
        for (int o = 16; o; o >>= 1) m = fmaxf(m, __shfl_xor_sync(0xffffffffu, m, o));
        float e = (lane < NT) ? expf(val - m) : 0.f;
        float se = e;
#pragma unroll
        for (int o = 16; o; o >>= 1) se += __shfl_xor_sync(0xffffffffu, se, o);
        if (lane < NT) s->gate[bi * NT + lane] = e / se;
    }
    __syncthreads();

    // ---- gate-scale -> g_hg; LN in place (tf32-rounded) ----
    float* hgo = g_hg + (size_t)row0 * NH;
    {
        float ng0 = n_g[lane], ng1 = n_g[lane + 32], ng2 = n_g[lane + 64], ng3 = n_g[lane + 96];
        float nb0 = n_b[lane], nb1 = n_b[lane + 32], nb2 = n_b[lane + 64], nb3 = n_b[lane + 96];
        for (int r = wid; r < 120; r += 8) {
            float gt = s->gate[r];
            float x0 = s->hn[r * LDH + lane]      * gt;
            float x1 = s->hn[r * LDH + lane + 32] * gt;
            float x2 = s->hn[r * LDH + lane + 64] * gt;
            float x3 = s->hn[r * LDH + lane + 96] * gt;
            hgo[r * NH + lane]      = x0;
            hgo[r * NH + lane + 32] = x1;
            hgo[r * NH + lane + 64] = x2;
            hgo[r * NH + lane + 96] = x3;
            float su = x0 + x1 + x2 + x3;
            float sq = x0 * x0 + x1 * x1 + x2 * x2 + x3 * x3;
#pragma unroll
            for (int o = 16; o; o >>= 1) {
                su += __shfl_xor_sync(0xffffffffu, su, o);
                sq += __shfl_xor_sync(0xffffffffu, sq, o);
            }
            float mean = su * (1.f / 128.f);
            float rstd = rsqrtf(sq * (1.f / 128.f) - mean * mean + 1e-5f);
            s->hn[r * LDH + lane]      = f2tf32f((x0 - mean) * rstd * ng0 + nb0);
            s->hn[r * LDH + lane + 32] = f2tf32f((x1 - mean) * rstd * ng1 + nb1);
            s->hn[r * LDH + lane + 64] = f2tf32f((x2 - mean) * rstd * ng2 + nb2);
            s->hn[r * LDH + lane + 96] = f2tf32f((x3 - mean) * rstd * ng3 + nb3);
        }
    }
    __syncthreads();

    // ---- qkv GEMM: A resident (hn), B single-buffer with reg prefetch ----
    int wm = (wid >> 2) * 64, wn = (wid & 3) * 32;
    int tr = lane >> 2, tc = lane & 3;
    uint32_t hnb = smem_u32(&s->hn[0]);
    uint32_t Bb  = smem_u32(&s->w.Bb[0]);

    float4 vrB[4];
#pragma unroll
    for (int q = 0; q < 4; q++) {
        int idx = tid + 256 * q;
        int kk = idx >> 5, jc = idx & 31;
        vrB[q] = *(const float4*)(g_Wqkvr + (size_t)kk * 384 + jc * 4);
    }
#pragma unroll
    for (int q = 0; q < 4; q++) {
        int idx = tid + 256 * q;
        int kk = idx >> 5, jc = idx & 31;
        sts128(Bb + (kk * LDB_S + jc * 4) * 4,
               __float_as_uint(vrB[q].x), __float_as_uint(vrB[q].y),
               __float_as_uint(vrB[q].z), __float_as_uint(vrB[q].w));
    }
    __syncthreads();

    float acc[4][4][4];
    ACC_INIT4(acc);
    for (int c = 0; c < 12; c++) {          // 3 ntiles x 4 k-chunks
        int ntile = c >> 2, it = c & 3;
        if (c + 1 < 12) {
            int nt2 = (c + 1) >> 2, it2 = (c + 1) & 3;
            int n0 = nt2 * 128, k0 = it2 * 32;
#pragma unroll
            for (int q = 0; q < 4; q++) {
                int idx = tid + 256 * q;
                int kk = idx >> 5, jc = idx & 31;
                vrB[q] = *(const float4*)(g_Wqkvr + (size_t)(k0 + kk) * 384 + n0 + jc * 4);
            }
        }
        mm_frag<4, LDH, false>(hnb, Bb, it * 32, lane, wm, wn, acc);

        if (it == 3) {
            // epilogue for this ntile: q / kT / v into smem
#pragma unroll
            for (int mt = 0; mt < 4; mt++) {
#pragma unroll
                for (int nt = 0; nt < 4; nt++) {
                    int colL = wn + nt * 8 + 2 * tc;
                    float bb0 = s->parb[ntile * 128 + colL];
                    float bb1 = s->parb[ntile * 128 + colL + 1];
#pragma unroll
                    for (int h = 0; h < 2; h++) {
                        int row = wm + mt * 16 + tr + 8 * h;
                        if (row < 120) {
                            float v0 = acc[mt][nt][2 * h]     + bb0;
                            float v1 = acc[mt][nt][2 * h + 1] + bb1;
                            if (ntile == 0) {
                                s->q[row * 128 + colL]     = v0;
                                s->q[row * 128 + colL + 1] = v1;
                            } else if (ntile == 1) {
                                s->kT[colL * LDH + row]       = v0;
                                s->kT[(colL + 1) * LDH + row] = v1;
                            } else {
                                // v overwrites hn (A no longer needed after this
                                // ntile's last mm_frag; barrier below orders it)
                                s->hn[row * LDH + colL]     = v0;
                                s->hn[row * LDH + colL + 1] = v1;
                            }
                        }
                    }
                }
            }
            ACC_INIT4(acc);
        }
        __syncthreads();                     // all warps done with Bb (and hn for ntile2)
        if (c + 1 < 12) {
#pragma unroll
            for (int q = 0; q < 4; q++) {
                int idx = tid + 256 * q;
                int kk = idx >> 5, jc = idx & 31;
                sts128(Bb + (kk * LDB_S + jc * 4) * 4,
                       __float_as_uint(vrB[q].x), __float_as_uint(vrB[q].y),
                       __float_as_uint(vrB[q].z), __float_as_uint(vrB[q].w));
            }
            __syncthreads();
        }
    }
    // NOTE: ntile2 epilogue writes v into hn AFTER the final mm_frag of ntile2;
    // the __syncthreads() before the epilogue's surrounding iteration boundary
    // (previous chunk sync) + the fact that all mm_frag reads of hn for ntile2
    // complete before 'it==3' epilogue executes in-warp is warp-local; the
    // cross-warp hazard is covered because every warp finishes its ntile2
    // mm_frag before ITS OWN epilogue, and other warps' epilogues write only
    // rows they own... (rows overlap across warps' A-reads!) -> need a barrier:
    __syncthreads();

    // ---- attention: scores + softmax ----
    const float SCALE = 0.08838834764831845f;   // sqrt(1/128)
    float* sc = s->w.sc;                         // reuse Bb region
    for (int r = wid; r < 120; r += 8) {
        int bi = r / NT;
        int kbase = bi * NT;
        float a = 0.f;
#pragma unroll 16
        for (int j = 0; j < 128; j++)
            a += s->q[r * 128 + j] * s->kT[j * LDH + kbase + lane];
        float val = (lane < NT) ? a * SCALE : -1e30f;
        float m = val;
#pragma unroll
        for (int o = 16; o; o >>= 1) m = fmaxf(m, __shfl_xor_sync(0xffffffffu, m, o));
        float e = (lane < NT) ? expf(val - m) : 0.f;
        float se = e;
#pragma unroll
        for (int o = 16; o; o >>= 1) se += __shfl_xor_sync(0xffffffffu, se, o);
        sc[r * 32 + lane] = e / se;
    }
    __syncthreads();

    // ---- o = sc @ v -> g_o ----
    {
        int col = tid & 127, rp = tid >> 7;
        float* ob = g_o + (size_t)row0 * NH;
#pragma unroll
        for (int bi = 0; bi < 4; bi++) {
            float accv[15];
#pragma unroll
            for (int j = 0; j < 15; j++) accv[j] = 0.f;
#pragma unroll
            for (int u = 0; u < NT; u++) {
                float vv = s->hn[(bi * NT + u) * LDH + col];
#pragma unroll
                for (int j = 0; j < 15; j++)
                    accv[j] += sc[(bi * NT + rp + 2 * j) * 32 + u] * vv;
            }
#pragma unroll
            for (int j = 0; j < 15; j++)
                ob[(bi * NT + rp + 2 * j) * NH + col] = accv[j];
        }
    }
}

// ---------------------------------------------------------------------------
// k_oproj2 (unchanged R15 winner)
// ---------------------------------------------------------------------------
__global__ __launch_bounds__(256, 2) void k_oproj2(
    const float* __restrict__ bo, const float* __restrict__ b2,
    float* __restrict__ out)
{
    extern __shared__ char smraw[];
    SmemO2* s = (SmemO2*)smraw;
    int tid = threadIdx.x;
    int lane = tid & 31, wid = tid >> 5;
    int row0 = blockIdx.x * M1;
    int wm = (wid >> 2) * 80, wn = (wid & 3) * 32;

    if (tid < 128) s->parb[tid] = bo[tid];
    uint32_t ub = smem_u32(&s->u[0]);
    uint32_t aA[2] = { ub + K1_A0 * 4, ub + K1_A1 * 4 };
    uint32_t aB[2] = { ub + K1_B0 * 4, ub + K1_B1 * 4 };

    float acc[5][4][4];
    ACC_INIT5(acc);

    cpA(aA[0], g_o, NH, row0, 0, tid);
    cpB(aB[0], g_Wor, NH, 0, 0, tid);
    CP_COMMIT(); CP_WAIT0();
    __syncthreads();

    int buf = 0;
    for (int it = 0; it < 4; it++) {
        bool pf = (it + 1 < 4);
        if (pf) {
            cpA(aA[buf ^ 1], g_o, NH, row0, (it + 1) * 32, tid);
            cpB(aB[buf ^ 1], g_Wor, NH, 0, (it + 1) * 32, tid);
            CP_COMMIT();
        }
        mm_frag<5, LDA_S, true>(aA[buf], aB[buf], 0, lane, wm, wn, acc);
        CP_WAIT0();
        __syncthreads();
        buf ^= 1;
    }

    int tr = lane >> 2, tc = lane & 3;
    float* hbuf = s->u;
#pragma unroll
    for (int mt = 0; mt < 5; mt++) {
#pragma unroll
        for (int nt = 0; nt < 4; nt++) {
            int colL = wn + nt * 8 + 2 * tc;
            float bb0 = s->parb[colL], bb1 = s->parb[colL + 1];
            int row = wm + mt * 16 + tr;
            {
                int grow = row0 + row;
                float v0 = 0.f, v1 = 0.f;
                if (grow < NM) {
                    float2 rres = *(const float2*)(g_hg + (size_t)grow * NH + colL);
                    v0 = acc[mt][nt][0] + bb0 + rres.x;
                    v1 = acc[mt][nt][1] + bb1 + rres.y;
                }
                hbuf[row * LDE_S + colL]     = f2tf32f(v0);
                hbuf[row * LDE_S + colL + 1] = f2tf32f(v1);
            }
            {
                int grow = row0 + row + 8;
                float v2 = 0.f, v3 = 0.f;
                if (grow < NM) {
                    float2 rres = *(const float2*)(g_hg + (size_t)grow * NH + colL);
                    v2 = acc[mt][nt][2] + bb0 + rres.x;
                    v3 = acc[mt][nt][3] + bb1 + rres.y;
                }
                hbuf[(row + 8) * LDE_S + colL]     = f2tf32f(v2);
                hbuf[(row + 8) * LDE_S + colL + 1] = f2tf32f(v3);
            }
        }
    }
    __syncthreads();

    uint32_t hb = ub;
    uint32_t Bb = smem_u32(&s->Bb[0]);

    float4 vrB[4];
#pragma unroll
    for (int q = 0; q < 4; q++) {
        int idx = tid + 256 * q;
        int kk = idx >> 5, jc = idx & 31;
        vrB[q] = *(const float4*)(g_W2r + (size_t)kk * ND + jc * 4);
    }
#pragma unroll
    for (int q = 0; q < 4; q++) {
        int idx = tid + 256 * q;
        int kk = idx >> 5, jc = idx & 31;
        sts128(Bb + (kk * LDB_S + jc * 4) * 4,
               __float_as_uint(vrB[q].x), __float_as_uint(vrB[q].y),
               __float_as_uint(vrB[q].z), __float_as_uint(vrB[q].w));
    }
    __syncthreads();

    ACC_INIT5(acc);
    for (int c = 0; c < 32; c++) {
        int nt = c >> 2, it = c & 3;
        if (c + 1 < 32) {
            int nt2 = (c + 1) >> 2, it2 = (c + 1) & 3;
            int n0 = nt2 * 128, k0 = it2 * 32;
#pragma unroll
            for (int q = 0; q < 4; q++) {
                int idx = tid + 256 * q;
                int kk = idx >> 5, jc = idx & 31;
                vrB[q] = *(const float4*)(g_W2r + (size_t)(k0 + kk) * ND + n0 + jc * 4);
            }
        }
        mm_frag<5, LDE_S, false>(hb, Bb, it * 32, lane, wm, wn, acc);

        if (it == 3) {
            int n0 = nt * 128;
#pragma unroll
            for (int mt = 0; mt < 5; mt++) {
#pragma unroll
                for (int nt2 = 0; nt2 < 4; nt2++) {
                    int colL = wn + nt2 * 8 + 2 * tc;
                    int col  = n0 + colL;
                    float bb0 = __ldg(b2 + col), bb1 = __ldg(b2 + col + 1);
                    int row = row0 + wm + mt * 16 + tr;
                    if (row < NM)
                        *(float2*)(out + (size_t)row * ND + col) =
                            make_float2(acc[mt][nt2][0] + bb0, acc[mt][nt2][1] + bb1);
                    if (row + 8 < NM)
                        *(float2*)(out + (size_t)(row + 8) * ND + col) =
                            make_float2(acc[mt][nt2][2] + bb0, acc[mt][nt2][3] + bb1);
                }
            }
            ACC_INIT5(acc);
        }
        __syncthreads();
        if (c + 1 < 32) {
#pragma unroll
            for (int q = 0; q < 4; q++) {
                int idx = tid + 256 * q;
                int kk = idx >> 5, jc = idx & 31;
                sts128(Bb + (kk * LDB_S + jc * 4) * 4,
                       __float_as_uint(vrB[q].x), __float_as_uint(vrB[q].y),
                       __float_as_uint(vrB[q].z), __float_as_uint(vrB[q].w));
            }
            __syncthreads();
        }
    }
}

extern "C" void kernel_launch(void* const* d_in, const int* in_sizes, int n_in,
                              void* d_out, int out_size)
{
    const float* x    = (const float*)d_in[0];
    const float* W1   = (const float*)d_in[1];
    const float* b1   = (const float*)d_in[2];
    const float* ln_g = (const float*)d_in[3];
    const float* ln_b = (const float*)d_in[4];
    const float* T_W  = (const float*)d_in[5];
    const float* T_b  = (const float*)d_in[6];
    const float* Wq   = (const float*)d_in[7];
    const float* bq   = (const float*)d_in[8];
    const float* Wk   = (const float*)d_in[9];
    const float* bk   = (const float*)d_in[10];
    const float* Wv   = (const float*)d_in[11];
    const float* bv   = (const float*)d_in[12];
    const float* Wo   = (const float*)d_in[13];
    const float* bo   = (const float*)d_in[14];
    const float* n_g  = (const float*)d_in[15];
    const float* n_b  = (const float*)d_in[16];
    const float* W2   = (const float*)d_in[17];
    const float* b2   = (const float*)d_in[18];
    float* out = (float*)d_out;

    int dynG1 = (int)sizeof(SmemG1);
    int dynF  = (int)sizeof(SmemF);
    int dynO2 = (int)sizeof(SmemO2);
    cudaFuncSetAttribute(k1_mma,    cudaFuncAttributeMaxDynamicSharedMemorySize, dynG1);
    cudaFuncSetAttribute(k_gateatt, cudaFuncAttributeMaxDynamicSharedMemorySize, dynF);
    cudaFuncSetAttribute(k_oproj2,  cudaFuncAttributeMaxDynamicSharedMemorySize, dynO2);

    const int PREP_N = ND * NH + NH * ND + NH * NH + 3 * NH * NH + 384;
    k_prep<<<(PREP_N + 255) / 256, 256>>>(W1, W2, Wo, Wq, Wk, Wv, bq, bk, bv);

    k1_mma<<<GM1, 256, dynG1>>>(x, b1, ln_g, ln_b);
    k_gateatt<<<NB / 4, 256, dynF>>>(T_W, T_b, n_g, n_b);
    k_oproj2<<<GM1, 256, dynO2>>>(bo, b2, out);
}

// round 17
// speedup vs baseline: 1.1106x; 1.1106x over previous
#include <cuda_runtime.h>
#include <math.h>
#include <stdint.h>

#define NB 1576
#define NT 30
#define ND 1024
#define NH 128
#define NM (NB*NT)   // 47280

// scratch
__device__ float g_h  [(size_t)NM * NH];
__device__ float g_hg [(size_t)NM * NH];
__device__ float g_o  [(size_t)NM * NH];
__device__ float g_qkv[(size_t)NM * 384];
__device__ float g_W1t[(size_t)NH * ND];    // W1^T  [128 n][1024 k], tf32
__device__ float g_W2t[(size_t)ND * NH];    // W2^T  [1024 n][128 k], tf32
__device__ float g_Wot[(size_t)NH * NH];    // Wo^T  [128 n][128 k], tf32
__device__ float g_Wqkvt[(size_t)384 * NH]; // [Wq|Wk|Wv]^T [384 n][128 k], tf32
__device__ float g_bqkv[384];

__device__ __forceinline__ uint32_t smem_u32(const void* p) {
    uint32_t a;
    asm("{ .reg .u64 t; cvta.to.shared.u64 t, %1; cvt.u32.u64 %0, t; }" : "=r"(a) : "l"(p));
    return a;
}
__device__ __forceinline__ uint32_t f2tf32(float f) {
    uint32_t r; asm("cvt.rna.tf32.f32 %0, %1;" : "=r"(r) : "f"(f)); return r;
}
__device__ __forceinline__ float f2tf32f(float f) { return __uint_as_float(f2tf32(f)); }
__device__ __forceinline__ uint32_t cvt_raw_tf32(uint32_t raw) {
    uint32_t r; asm("cvt.rna.tf32.f32 %0, %1;" : "=r"(r) : "f"(__uint_as_float(raw)));
    return r;
}
__device__ __forceinline__ void sts128(uint32_t a, uint32_t x, uint32_t y, uint32_t z, uint32_t w) {
    asm volatile("st.shared.v4.b32 [%0], {%1,%2,%3,%4};" :: "r"(a), "r"(x), "r"(y), "r"(z), "r"(w));
}
__device__ __forceinline__ void ldsm4(uint32_t& r0, uint32_t& r1, uint32_t& r2, uint32_t& r3,
                                      uint32_t addr) {
    asm volatile("ldmatrix.sync.aligned.m8n8.x4.shared.b16 {%0,%1,%2,%3}, [%4];"
                 : "=r"(r0), "=r"(r1), "=r"(r2), "=r"(r3) : "r"(addr));
}
__device__ __forceinline__ void cp16(uint32_t dst, const void* src) {
    asm volatile("cp.async.cg.shared.global [%0], [%1], 16;" :: "r"(dst), "l"(src));
}
__device__ __forceinline__ void cp16z(uint32_t dst, const void* src, uint32_t sz) {
    asm volatile("cp.async.cg.shared.global [%0], [%1], 16, %2;"
                 :: "r"(dst), "l"(src), "r"(sz));
}
#define CP_COMMIT() asm volatile("cp.async.commit_group;" ::: "memory")
#define CP_WAIT0()  asm volatile("cp.async.wait_group 0;" ::: "memory")

#define LDA_S 36
#define LDBT  36      // transposed-B staging stride ([128 n][36])
#define LDE_S 132
#define LDH   132
#define M1    160
#define GM1   296

// k1 / oproj2-phase1 buffer offsets inside the 21120-float union
#define K1_A0   0
#define K1_A1   (M1*LDA_S)                 // 5760
#define K1_B0   (2*M1*LDA_S)               // 11520
#define K1_B1   (2*M1*LDA_S + 128*LDBT)    // 16128
#define K1_UNION 21120
struct SmemG1 {
    float u[K1_UNION];
    float parb[128];
    float parg[128];
    float parbt[128];
    float mean[M1];
    float rstd[M1];
};
struct SmemO2 {
    float u[K1_UNION];
    float Bb[128 * LDBT];
    float parb[128];
};
struct SmemQ {
    float hn[128 * LDH];
    float Bb[2][128 * LDBT];
    float rowm[120];
    float gate[120];
    float parb[384];
};

// ---------------------------------------------------------------------------
// prep: tf32-round + TRANSPOSE all weights to [N][K]; pack bqkv
// ---------------------------------------------------------------------------
__global__ void k_prep(const float* __restrict__ W1, const float* __restrict__ W2,
                       const float* __restrict__ Wo,
                       const float* __restrict__ Wq, const float* __restrict__ Wk,
                       const float* __restrict__ Wv,
                       const float* __restrict__ bq, const float* __restrict__ bk,
                       const float* __restrict__ bv) {
    int i = blockIdx.x * 256 + threadIdx.x;
    const int N1 = NH * ND;        // W1t elements
    const int N2 = ND * NH;        // W2t
    const int N3 = NH * NH;        // Wot
    const int N4 = 384 * NH;       // Wqkvt
    if (i < N1) {
        int n = i >> 10, k = i & 1023;           // W1t[n][k] = W1[k][n]
        g_W1t[i] = f2tf32f(W1[(size_t)k * NH + n]);
    } else if (i < N1 + N2) {
        int j = i - N1;
        int n = j >> 7, k = j & 127;             // W2t[n][k] = W2[k][n]
        g_W2t[j] = f2tf32f(W2[(size_t)k * ND + n]);
    } else if (i < N1 + N2 + N3) {
        int j = i - N1 - N2;
        int n = j >> 7, k = j & 127;             // Wot[n][k] = Wo[k][n]
        g_Wot[j] = f2tf32f(Wo[(size_t)k * NH + n]);
    } else if (i < N1 + N2 + N3 + N4) {
        int j = i - N1 - N2 - N3;
        int col = j >> 7, k = j & 127;           // col in [0,384)
        int m = col >> 7, n = col & 127;
        const float* W = (m == 0) ? Wq : (m == 1) ? Wk : Wv;
        g_Wqkvt[j] = f2tf32f(W[(size_t)k * NH + n]);
    } else if (i < N1 + N2 + N3 + N4 + 384) {
        int j = i - N1 - N2 - N3 - N4;
        int m = j / NH, n = j % NH;
        const float* bb = (m == 0) ? bq : (m == 1) ? bk : bv;
        g_bqkv[j] = bb[n];
    }
}

// ---------------------------------------------------------------------------
// staging
// ---------------------------------------------------------------------------
__device__ __forceinline__ void cpA(uint32_t As, const float* __restrict__ Ag,
                                    int ldA, int row0, int k0, int tid) {
#pragma unroll
    for (int q = 0; q < 5; q++) {
        int idx = tid + 256 * q;
        int r = idx >> 3, j = idx & 7;
        int row = row0 + r;
        uint32_t sz = (row < NM) ? 16u : 0u;
        const float* src = Ag + (size_t)(row < NM ? row : 0) * ldA + k0 + j * 4;
        cp16z(As + (r * LDA_S + j * 4) * 4, src, sz);
    }
}
// transposed B: stage [128 n][32 k] from Bt[n][k] (row stride ldK)
__device__ __forceinline__ void cpBt(uint32_t Bs, const float* __restrict__ Bt,
                                     int ldK, int n0, int k0, int tid) {
#pragma unroll
    for (int q = 0; q < 4; q++) {
        int idx = tid + 256 * q;
        int r = idx >> 3, j = idx & 7;
        cp16(Bs + (r * LDBT + j * 4) * 4,
             Bt + (size_t)(n0 + r) * ldK + k0 + j * 4);
    }
}

// ---------------------------------------------------------------------------
// LDSM-based fragment compute. A stride LD (36 or 132), B stride LDBT=36.
// ---------------------------------------------------------------------------
template<int MT, int LD, bool CVT>
__device__ __forceinline__ void mm_frag(uint32_t Ab, uint32_t Bs, int kbase,
                                        int lane, int wm, int wn,
                                        float acc[MT][4][4]) {
    // per-lane LDSM row/col selectors
    int rA = (lane & 7) + 8 * ((lane >> 3) & 1);   // row within 16-row m-tile
    int cA = 4 * (lane >> 4);                       // k sub-offset 0/4
    int rB = ((lane >> 4) * 8) + (lane & 7);        // n within 16-col group
    int kB = 4 * ((lane >> 3) & 1);                 // k sub-offset 0/4
#pragma unroll
    for (int ks = 0; ks < 4; ks++) {
        int ka = kbase + ks * 8;
        int kb = ks * 8;
        uint32_t af[MT][4];
#pragma unroll
        for (int mt = 0; mt < MT; mt++) {
            uint32_t a = Ab + (((wm + mt * 16 + rA) * LD) + ka + cA) * 4;
            ldsm4(af[mt][0], af[mt][1], af[mt][2], af[mt][3], a);
        }
        uint32_t bf[4][2];
        {
            uint32_t b0 = Bs + (((wn + rB) * LDBT) + kb + kB) * 4;
            ldsm4(bf[0][0], bf[0][1], bf[1][0], bf[1][1], b0);
            uint32_t b1 = Bs + (((wn + 16 + rB) * LDBT) + kb + kB) * 4;
            ldsm4(bf[2][0], bf[2][1], bf[3][0], bf[3][1], b1);
        }
        if (CVT) {
#pragma unroll
            for (int mt = 0; mt < MT; mt++) {
                af[mt][0] = cvt_raw_tf32(af[mt][0]);
                af[mt][1] = cvt_raw_tf32(af[mt][1]);
                af[mt][2] = cvt_raw_tf32(af[mt][2]);
                af[mt][3] = cvt_raw_tf32(af[mt][3]);
            }
        }
#pragma unroll
        for (int mt = 0; mt < MT; mt++)
#pragma unroll
            for (int nt = 0; nt < 4; nt++)
                asm volatile(
                    "mma.sync.aligned.m16n8k8.row.col.f32.tf32.tf32.f32 "
                    "{%0,%1,%2,%3}, {%4,%5,%6,%7}, {%8,%9}, {%0,%1,%2,%3};"
                    : "+f"(acc[mt][nt][0]), "+f"(acc[mt][nt][1]),
                      "+f"(acc[mt][nt][2]), "+f"(acc[mt][nt][3])
                    : "r"(af[mt][0]), "r"(af[mt][1]), "r"(af[mt][2]), "r"(af[mt][3]),
                      "r"(bf[nt][0]), "r"(bf[nt][1]));
    }
}

#define ACC_INIT5(acc) \
    _Pragma("unroll") for (int a_ = 0; a_ < 5; a_++) \
    _Pragma("unroll") for (int b_ = 0; b_ < 4; b_++) { \
        acc[a_][b_][0]=0.f; acc[a_][b_][1]=0.f; acc[a_][b_][2]=0.f; acc[a_][b_][3]=0.f; }
#define ACC_INIT4(acc) \
    _Pragma("unroll") for (int a_ = 0; a_ < 4; a_++) \
    _Pragma("unroll") for (int b_ = 0; b_ < 4; b_++) { \
        acc[a_][b_][0]=0.f; acc[a_][b_][1]=0.f; acc[a_][b_][2]=0.f; acc[a_][b_][3]=0.f; }

// ---------------------------------------------------------------------------
// GEMM1: h = LayerNorm(x @ W1 + b1), M-tile 160, grid 296 (2/SM)
// ---------------------------------------------------------------------------
__global__ __launch_bounds__(256, 2) void k1_mma(
    const float* __restrict__ x, const float* __restrict__ b1,
    const float* __restrict__ ln_g, const float* __restrict__ ln_b)
{
    extern __shared__ char smraw[];
    SmemG1* s = (SmemG1*)smraw;
    int tid = threadIdx.x;
    int lane = tid & 31, wid = tid >> 5;
    int row0 = blockIdx.x * M1;
    int wm = (wid >> 2) * 80, wn = (wid & 3) * 32;

    if (tid < 128) {
        s->parb[tid]  = b1[tid];
        s->parg[tid]  = ln_g[tid];
        s->parbt[tid] = ln_b[tid];
    }
    uint32_t ub = smem_u32(&s->u[0]);
    uint32_t aA[2] = { ub + K1_A0 * 4, ub + K1_A1 * 4 };
    uint32_t aB[2] = { ub + K1_B0 * 4, ub + K1_B1 * 4 };

    float acc[5][4][4];
    ACC_INIT5(acc);

    cpA(aA[0], x, ND, row0, 0, tid);
    cpBt(aB[0], g_W1t, ND, 0, 0, tid);
    CP_COMMIT(); CP_WAIT0();
    __syncthreads();

    int buf = 0;
    for (int it = 0; it < ND / 32; it++) {
        bool pf = (it + 1 < ND / 32);
        if (pf) {
            cpA(aA[buf ^ 1], x, ND, row0, (it + 1) * 32, tid);
            cpBt(aB[buf ^ 1], g_W1t, ND, 0, (it + 1) * 32, tid);
            CP_COMMIT();
        }
        mm_frag<5, LDA_S, true>(aA[buf], aB[buf], 0, lane, wm, wn, acc);
        CP_WAIT0();
        __syncthreads();
        buf ^= 1;
    }

    int tr = lane >> 2, tc = lane & 3;
    float* epi = s->u;
#pragma unroll
    for (int mt = 0; mt < 5; mt++) {
#pragma unroll
        for (int nt = 0; nt < 4; nt++) {
            int row = wm + mt * 16 + tr;
            int col = wn + nt * 8 + 2 * tc;
            float bb0 = s->parb[col], bb1 = s->parb[col + 1];
            epi[row * LDE_S + col]           = acc[mt][nt][0] + bb0;
            epi[row * LDE_S + col + 1]       = acc[mt][nt][1] + bb1;
            epi[(row + 8) * LDE_S + col]     = acc[mt][nt][2] + bb0;
            epi[(row + 8) * LDE_S + col + 1] = acc[mt][nt][3] + bb1;
        }
    }
    __syncthreads();

    for (int r = wid; r < M1; r += 8) {
        float x0 = epi[r * LDE_S + lane];
        float x1 = epi[r * LDE_S + lane + 32];
        float x2 = epi[r * LDE_S + lane + 64];
        float x3 = epi[r * LDE_S + lane + 96];
        float su = x0 + x1 + x2 + x3;
        float sq = x0 * x0 + x1 * x1 + x2 * x2 + x3 * x3;
#pragma unroll
        for (int o = 16; o; o >>= 1) {
            su += __shfl_xor_sync(0xffffffffu, su, o);
            sq += __shfl_xor_sync(0xffffffffu, sq, o);
        }
        float mean = su * (1.f / 128.f);
        float var  = sq * (1.f / 128.f) - mean * mean;
        if (lane == 0) {
            s->mean[r] = mean;
            s->rstd[r] = rsqrtf(fmaxf(var, 0.f) + 1e-5f);
        }
    }
    __syncthreads();

#pragma unroll
    for (int q = 0; q < 20; q++) {
        int idx = tid + 256 * q;
        int r = idx >> 5, c4 = idx & 31;
        int row = row0 + r;
        if (row < NM) {
            float4 v = *(float4*)&epi[r * LDE_S + 4 * c4];
            float mean = s->mean[r], rstd = s->rstd[r];
            float4 gv = *(float4*)&s->parg[4 * c4];
            float4 bv = *(float4*)&s->parbt[4 * c4];
            float4 o;
            o.x = (v.x - mean) * rstd * gv.x + bv.x;
            o.y = (v.y - mean) * rstd * gv.y + bv.y;
            o.z = (v.z - mean) * rstd * gv.z + bv.z;
            o.w = (v.w - mean) * rstd * gv.w + bv.w;
            *(float4*)(g_h + (size_t)row * NH + 4 * c4) = o;
        }
    }
}

// ---------------------------------------------------------------------------
// k_gateqkv: gate + LN + qkv GEMM (A resident), 4 batches/block
// ---------------------------------------------------------------------------
__global__ __launch_bounds__(256) void k_gateqkv(
    const float* __restrict__ T_W, const float* __restrict__ T_b,
    const float* __restrict__ n_g, const float* __restrict__ n_b)
{
    extern __shared__ char smraw[];
    SmemQ* s = (SmemQ*)smraw;
    int tid = threadIdx.x;
    int lane = tid & 31, wid = tid >> 5;
    int row0 = blockIdx.x * 4 * NT;
    const float* hg = g_h + (size_t)row0 * NH;

    for (int i = tid; i < 384; i += 256) s->parb[i] = g_bqkv[i];

    for (int idx = tid; idx < 120 * 32; idx += 256) {
        int r = idx >> 5, c4 = idx & 31;
        float4 t = *(const float4*)(hg + (size_t)r * NH + 4 * c4);
        *(float4*)&s->hn[r * LDH + 4 * c4] = t;
    }
    for (int idx = tid; idx < 8 * 32; idx += 256) {
        int r = 120 + (idx >> 5), c4 = idx & 31;
        *(float4*)&s->hn[r * LDH + 4 * c4] = make_float4(0.f, 0.f, 0.f, 0.f);
    }
    __syncthreads();

    for (int r = wid; r < 120; r += 8) {
        float a = s->hn[r * LDH + lane] + s->hn[r * LDH + lane + 32]
                + s->hn[r * LDH + lane + 64] + s->hn[r * LDH + lane + 96];
#pragma unroll
        for (int o = 16; o; o >>= 1) a += __shfl_xor_sync(0xffffffffu, a, o);
        if (lane == 0) s->rowm[r] = a * (1.f / 128.f);
    }
    __syncthreads();

    if (wid < 4) {
        int bi = wid;
        float val = -1e30f;
        if (lane < NT) {
            float a = T_b[lane];
#pragma unroll
            for (int u = 0; u < NT; u++) a += s->rowm[bi * NT + u] * T_W[u * NT + lane];
            val = a;
        }
        float m = val;
#pragma unroll
        for (int o = 16; o; o >>= 1) m = fmaxf(m, __shfl_xor_sync(0xffffffffu, m, o));
        float e = (lane < NT) ? expf(val - m) : 0.f;
        float se = e;
#pragma unroll
        for (int o = 16; o; o >>= 1) se += __shfl_xor_sync(0xffffffffu, se, o);
        if (lane < NT) s->gate[bi * NT + lane] = e / se;
    }
    __syncthreads();

    float* hgo = g_hg + (size_t)row0 * NH;
    {
        float ng0 = n_g[lane], ng1 = n_g[lane + 32], ng2 = n_g[lane + 64], ng3 = n_g[lane + 96];
        float nb0 = n_b[lane], nb1 = n_b[lane + 32], nb2 = n_b[lane + 64], nb3 = n_b[lane + 96];
        for (int r = wid; r < 120; r += 8) {
            float gt = s->gate[r];
            float x0 = s->hn[r * LDH + lane]      * gt;
            float x1 = s->hn[r * LDH + lane + 32] * gt;
            float x2 = s->hn[r * LDH + lane + 64] * gt;
            float x3 = s->hn[r * LDH + lane + 96] * gt;
            hgo[r * NH + lane]      = x0;
            hgo[r * NH + lane + 32] = x1;
            hgo[r * NH + lane + 64] = x2;
            hgo[r * NH + lane + 96] = x3;
            float su = x0 + x1 + x2 + x3;
            float sq = x0 * x0 + x1 * x1 + x2 * x2 + x3 * x3;
#pragma unroll
            for (int o = 16; o; o >>= 1) {
                su += __shfl_xor_sync(0xffffffffu, su, o);
                sq += __shfl_xor_sync(0xffffffffu, sq, o);
            }
            float mean = su * (1.f / 128.f);
            float rstd = rsqrtf(sq * (1.f / 128.f) - mean * mean + 1e-5f);
            s->hn[r * LDH + lane]      = f2tf32f((x0 - mean) * rstd * ng0 + nb0);
            s->hn[r * LDH + lane + 32] = f2tf32f((x1 - mean) * rstd * ng1 + nb1);
            s->hn[r * LDH + lane + 64] = f2tf32f((x2 - mean) * rstd * ng2 + nb2);
            s->hn[r * LDH + lane + 96] = f2tf32f((x3 - mean) * rstd * ng3 + nb3);
        }
    }
    __syncthreads();

    int wm = (wid >> 2) * 64, wn = (wid & 3) * 32;
    int tr = lane >> 2, tc = lane & 3;
    uint32_t hnb = smem_u32(&s->hn[0]);
    uint32_t aB[2] = { smem_u32(&s->Bb[0][0]), smem_u32(&s->Bb[1][0]) };

    for (int ntile = 0; ntile < 3; ntile++) {
        int n0 = ntile * 128;
        float acc[4][4][4];
        ACC_INIT4(acc);
        cpBt(aB[0], g_Wqkvt, NH, n0, 0, tid); CP_COMMIT(); CP_WAIT0(); __syncthreads();
        int buf = 0;
        for (int it = 0; it < 4; it++) {
            if (it < 3) { cpBt(aB[buf ^ 1], g_Wqkvt, NH, n0, (it + 1) * 32, tid); CP_COMMIT(); }
            mm_frag<4, LDH, false>(hnb, aB[buf], it * 32, lane, wm, wn, acc);
            CP_WAIT0(); __syncthreads();
            buf ^= 1;
        }
#pragma unroll
        for (int mt = 0; mt < 4; mt++) {
#pragma unroll
            for (int nt = 0; nt < 4; nt++) {
                int colL = wn + nt * 8 + 2 * tc;
                int col  = n0 + colL;
                float bb0 = s->parb[col], bb1 = s->parb[col + 1];
                int row = wm + mt * 16 + tr;
                if (row < 120)
                    *(float2*)(g_qkv + (size_t)(row0 + row) * 384 + col) =
                        make_float2(acc[mt][nt][0] + bb0, acc[mt][nt][1] + bb1);
                if (row + 8 < 120)
                    *(float2*)(g_qkv + (size_t)(row0 + row + 8) * 384 + col) =
                        make_float2(acc[mt][nt][2] + bb0, acc[mt][nt][3] + bb1);
            }
        }
    }
}

// ---------------------------------------------------------------------------
// k_att (R15 winner, unchanged)
// ---------------------------------------------------------------------------
struct SmemA {
    float q[NT][128];
    float kT[128][33];
    float v[NT][128];
    float sc[NT][32];
};
__global__ __launch_bounds__(256) void k_att()
{
    extern __shared__ char smraw[];
    SmemA* s = (SmemA*)smraw;
    int tid = threadIdx.x;
    int lane = tid & 31, wid = tid >> 5;
    int b = blockIdx.x;
    const float* qkv = g_qkv + (size_t)b * NT * 384;

    for (int idx = tid; idx < NT * 96; idx += 256) {
        int r = idx / 96, c4 = idx - (idx / 96) * 96;
        float4 t = *(const float4*)(qkv + (size_t)r * 384 + 4 * c4);
        if (c4 < 32) {
            *(float4*)&s->q[r][4 * c4] = t;
        } else if (c4 < 64) {
            int kc = 4 * (c4 - 32);
            s->kT[kc + 0][r] = t.x;
            s->kT[kc + 1][r] = t.y;
            s->kT[kc + 2][r] = t.z;
            s->kT[kc + 3][r] = t.w;
        } else {
            *(float4*)&s->v[r][4 * (c4 - 64)] = t;
        }
    }
    __syncthreads();

    const float SCALE = 0.08838834764831845f;
    {
        int t0 = wid, t1 = wid + 8, t2 = wid + 16, t3 = wid + 24;
        bool v3 = (t3 < NT);
        int t3c = v3 ? t3 : 0;
        float a0 = 0.f, a1 = 0.f, a2 = 0.f, a3 = 0.f;
#pragma unroll 16
        for (int j = 0; j < 128; j++) {
            float kv = s->kT[j][lane];
            a0 += s->q[t0][j] * kv;
            a1 += s->q[t1][j] * kv;
            a2 += s->q[t2][j] * kv;
            a3 += s->q[t3c][j] * kv;
        }
        float av[4] = {a0, a1, a2, a3};
        int   tv[4] = {t0, t1, t2, t3};
#pragma unroll
        for (int i = 0; i < 4; i++) {
            if (tv[i] >= NT) break;
            float val = (lane < NT) ? av[i] * SCALE : -1e30f;
            float m = val;
#pragma unroll
            for (int o = 16; o; o >>= 1) m = fmaxf(m, __shfl_xor_sync(0xffffffffu, m, o));
            float e = (lane < NT) ? expf(val - m) : 0.f;
            float se = e;
#pragma unroll
            for (int o = 16; o; o >>= 1) se += __shfl_xor_sync(0xffffffffu, se, o);
            s->sc[tv[i]][lane] = e / se;
        }
    }
    __syncthreads();

    {
        int col = tid & 127, rp = tid >> 7;
        float accv[15];
#pragma unroll
        for (int j = 0; j < 15; j++) accv[j] = 0.f;
#pragma unroll
        for (int u = 0; u < NT; u++) {
            float vv = s->v[u][col];
#pragma unroll
            for (int j = 0; j < 15; j++)
                accv[j] += s->sc[rp + 2 * j][u] * vv;
        }
        float* ob = g_o + (size_t)b * NT * NH;
#pragma unroll
        for (int j = 0; j < 15; j++)
            ob[(rp + 2 * j) * NH + col] = accv[j];
    }
}

// ---------------------------------------------------------------------------
// k_oproj2: phase1 oproj (+bias+residual, tf32 round -> hbuf);
//           phase2 out = h @ W2 + b2, 8 N-tiles, single-B reg-prefetch
// ---------------------------------------------------------------------------
__global__ __launch_bounds__(256, 2) void k_oproj2(
    const float* __restrict__ bo, const float* __restrict__ b2,
    float* __restrict__ out)
{
    extern __shared__ char smraw[];
    SmemO2* s = (SmemO2*)smraw;
    int tid = threadIdx.x;
    int lane = tid & 31, wid = tid >> 5;
    int row0 = blockIdx.x * M1;
    int wm = (wid >> 2) * 80, wn = (wid & 3) * 32;

    if (tid < 128) s->parb[tid] = bo[tid];
    uint32_t ub = smem_u32(&s->u[0]);
    uint32_t aA[2] = { ub + K1_A0 * 4, ub + K1_A1 * 4 };
    uint32_t aB[2] = { ub + K1_B0 * 4, ub + K1_B1 * 4 };

    float acc[5][4][4];
    ACC_INIT5(acc);

    cpA(aA[0], g_o, NH, row0, 0, tid);
    cpBt(aB[0], g_Wot, NH, 0, 0, tid);
    CP_COMMIT(); CP_WAIT0();
    __syncthreads();

    int buf = 0;
    for (int it = 0; it < 4; it++) {
        bool pf = (it + 1 < 4);
        if (pf) {
            cpA(aA[buf ^ 1], g_o, NH, row0, (it + 1) * 32, tid);
            cpBt(aB[buf ^ 1], g_Wot, NH, 0, (it + 1) * 32, tid);
            CP_COMMIT();
        }
        mm_frag<5, LDA_S, true>(aA[buf], aB[buf], 0, lane, wm, wn, acc);
        CP_WAIT0();
        __syncthreads();
        buf ^= 1;
    }

    int tr = lane >> 2, tc = lane & 3;
    float* hbuf = s->u;
#pragma unroll
    for (int mt = 0; mt < 5; mt++) {
#pragma unroll
        for (int nt = 0; nt < 4; nt++) {
            int colL = wn + nt * 8 + 2 * tc;
            float bb0 = s->parb[colL], bb1 = s->parb[colL + 1];
            int row = wm + mt * 16 + tr;
            {
                int grow = row0 + row;
                float v0 = 0.f, v1 = 0.f;
                if (grow < NM) {
                    float2 rres = *(const float2*)(g_hg + (size_t)grow * NH + colL);
                    v0 = acc[mt][nt][0] + bb0 + rres.x;
                    v1 = acc[mt][nt][1] + bb1 + rres.y;
                }
                hbuf[row * LDE_S + colL]     = f2tf32f(v0);
                hbuf[row * LDE_S + colL + 1] = f2tf32f(v1);
            }
            {
                int grow = row0 + row + 8;
                float v2 = 0.f, v3 = 0.f;
                if (grow < NM) {
                    float2 rres = *(const float2*)(g_hg + (size_t)grow * NH + colL);
                    v2 = acc[mt][nt][2] + bb0 + rres.x;
                    v3 = acc[mt][nt][3] + bb1 + rres.y;
                }
                hbuf[(row + 8) * LDE_S + colL]     = f2tf32f(v2);
                hbuf[(row + 8) * LDE_S + colL + 1] = f2tf32f(v3);
            }
        }
    }
    __syncthreads();

    uint32_t hb = ub;
    uint32_t Bb = smem_u32(&s->Bb[0]);

    // phase 2: B chunks are [128 n][32 k] slices of g_W2t
    float4 vrB[4];
#pragma unroll
    for (int q = 0; q < 4; q++) {
        int idx = tid + 256 * q;
        int r = idx >> 3, j = idx & 7;
        vrB[q] = *(const float4*)(g_W2t + (size_t)r * NH + j * 4);
    }
#pragma unroll
    for (int q = 0; q < 4; q++) {
        int idx = tid + 256 * q;
        int r = idx >> 3, j = idx & 7;
        sts128(Bb + (r * LDBT + j * 4) * 4,
               __float_as_uint(vrB[q].x), __float_as_uint(vrB[q].y),
               __float_as_uint(vrB[q].z), __float_as_uint(vrB[q].w));
    }
    __syncthreads();

    ACC_INIT5(acc);
    for (int c = 0; c < 32; c++) {
        int nt = c >> 2, it = c & 3;
        if (c + 1 < 32) {
            int nt2 = (c + 1) >> 2, it2 = (c + 1) & 3;
            int n0 = nt2 * 128, k0 = it2 * 32;
#pragma unroll
            for (int q = 0; q < 4; q++) {
                int idx = tid + 256 * q;
                int r = idx >> 3, j = idx & 7;
                vrB[q] = *(const float4*)(g_W2t + (size_t)(n0 + r) * NH + k0 + j * 4);
            }
        }
        mm_frag<5, LDE_S, false>(hb, Bb, it * 32, lane, wm, wn, acc);

        if (it == 3) {
            int n0 = nt * 128;
#pragma unroll
            for (int mt = 0; mt < 5; mt++) {
#pragma unroll
                for (int nt2 = 0; nt2 < 4; nt2++) {
                    int colL = wn + nt2 * 8 + 2 * tc;
                    int col  = n0 + colL;
                    float bb0 = __ldg(b2 + col), bb1 = __ldg(b2 + col + 1);
                    int row = row0 + wm + mt * 16 + tr;
                    if (row < NM)
                        *(float2*)(out + (size_t)row * ND + col) =
                            make_float2(acc[mt][nt2][0] + bb0, acc[mt][nt2][1] + bb1);
                    if (row + 8 < NM)
                        *(float2*)(out + (size_t)(row + 8) * ND + col) =
                            make_float2(acc[mt][nt2][2] + bb0, acc[mt][nt2][3] + bb1);
                }
            }
            ACC_INIT5(acc);
        }
        __syncthreads();
        if (c + 1 < 32) {
#pragma unroll
            for (int q = 0; q < 4; q++) {
                int idx = tid + 256 * q;
                int r = idx >> 3, j = idx & 7;
                sts128(Bb + (r * LDBT + j * 4) * 4,
                       __float_as_uint(vrB[q].x), __float_as_uint(vrB[q].y),
                       __float_as_uint(vrB[q].z), __float_as_uint(vrB[q].w));
            }
            __syncthreads();
        }
    }
}

extern "C" void kernel_launch(void* const* d_in, const int* in_sizes, int n_in,
                              void* d_out, int out_size)
{
    const float* x    = (const float*)d_in[0];
    const float* W1   = (const float*)d_in[1];
    const float* b1   = (const float*)d_in[2];
    const float* ln_g = (const float*)d_in[3];
    const float* ln_b = (const float*)d_in[4];
    const float* T_W  = (const float*)d_in[5];
    const float* T_b  = (const float*)d_in[6];
    const float* Wq   = (const float*)d_in[7];
    const float* bq   = (const float*)d_in[8];
    const float* Wk   = (const float*)d_in[9];
    const float* bk   = (const float*)d_in[10];
    const float* Wv   = (const float*)d_in[11];
    const float* bv   = (const float*)d_in[12];
    const float* Wo   = (const float*)d_in[13];
    const float* bo   = (const float*)d_in[14];
    const float* n_g  = (const float*)d_in[15];
    const float* n_b  = (const float*)d_in[16];
    const float* W2   = (const float*)d_in[17];
    const float* b2   = (const float*)d_in[18];
    float* out = (float*)d_out;

    int dynG1 = (int)sizeof(SmemG1);
    int dynQ  = (int)sizeof(SmemQ);
    int dynA  = (int)sizeof(SmemA);
    int dynO2 = (int)sizeof(SmemO2);
    cudaFuncSetAttribute(k1_mma,    cudaFuncAttributeMaxDynamicSharedMemorySize, dynG1);
    cudaFuncSetAttribute(k_gateqkv, cudaFuncAttributeMaxDynamicSharedMemorySize, dynQ);
    cudaFuncSetAttribute(k_att,     cudaFuncAttributeMaxDynamicSharedMemorySize, dynA);
    cudaFuncSetAttribute(k_oproj2,  cudaFuncAttributeMaxDynamicSharedMemorySize, dynO2);

    const int PREP_N = NH * ND + ND * NH + NH * NH + 384 * NH + 384;
    k_prep<<<(PREP_N + 255) / 256, 256>>>(W1, W2, Wo, Wq, Wk, Wv, bq, bk, bv);

    k1_mma<<<GM1, 256, dynG1>>>(x, b1, ln_g, ln_b);
    k_gateqkv<<<NB / 4, 256, dynQ>>>(T_W, T_b, n_g, n_b);
    k_att<<<NB, 256, dynA>>>();
    k_oproj2<<<GM1, 256, dynO2>>>(bo, b2, out);
}